// round 1
// baseline (speedup 1.0000x reference)
#include <cuda_runtime.h>

// EmbeddingLayer: 16 sparse gathers + 2 sequence poolings (sum, nonzero-mean) + dense concat.
//
// Shapes (from reference):
//   sparse_tables [16, 100000, 64] f32
//   seq_tables    [ 2, 100000, 64] f32
//   dense_vals    [4096, 13]       f32
//   sparse_idx    [16, 4096]       i32
//   seq_idx       [ 2, 4096, 50]   i32
//   out           [4096, 18*64+13 = 1165] f32

#define VOCAB   100000
#define BATCH   4096
#define EMBED   64
#define SEQLEN  50
#define NSPARSE 16
#define NDENSE  13
#define ROW_OUT (NSPARSE * EMBED + 2 * EMBED + NDENSE)  // 1165

#define ROWS_PER_BLOCK 16
#define THREADS (ROWS_PER_BLOCK * 16)  // 16 lanes (float4) per row

__global__ __launch_bounds__(THREADS)
void embedding_layer_kernel(const float4* __restrict__ sp_tab,   // [16*VOCAB*16] float4
                            const float4* __restrict__ seq_tab,  // [ 2*VOCAB*16] float4
                            const float*  __restrict__ dense,    // [BATCH*13]
                            const int*    __restrict__ sp_idx,   // [16*BATCH]
                            const int*    __restrict__ sq_idx,   // [2*BATCH*50]
                            float*        __restrict__ out)      // [BATCH*1165]
{
    const int tid = threadIdx.x;
    const int r   = tid >> 4;        // row within block (0..15)
    const int q   = tid & 15;        // float4 index within embed dim (0..15)
    const int b   = blockIdx.x * ROWS_PER_BLOCK + r;

    float* __restrict__ orow = out + (size_t)b * ROW_OUT;

    // ---- 16 sparse gathers: all independent -> 16 LDG.128 in flight ----
    #pragma unroll
    for (int f = 0; f < NSPARSE; f++) {
        int idx = __ldg(&sp_idx[f * BATCH + b]);
        float4 v = __ldg(&sp_tab[((size_t)f * VOCAB + idx) * 16 + q]);
        float* o = orow + f * EMBED + q * 4;
        o[0] = v.x; o[1] = v.y; o[2] = v.z; o[3] = v.w;
    }

    // ---- seq feature 0: sum pooling over 50 gathers ----
    {
        const int* __restrict__ ip = sq_idx + (size_t)b * SEQLEN;
        float4 acc = make_float4(0.f, 0.f, 0.f, 0.f);
        #pragma unroll 10
        for (int s = 0; s < SEQLEN; s++) {
            int idx = __ldg(&ip[s]);
            float4 v = __ldg(&seq_tab[(size_t)idx * 16 + q]);
            acc.x += v.x; acc.y += v.y; acc.z += v.z; acc.w += v.w;
        }
        float* o = orow + NSPARSE * EMBED + q * 4;
        o[0] = acc.x; o[1] = acc.y; o[2] = acc.z; o[3] = acc.w;
    }

    // ---- seq feature 1: mean over per-dim nonzero counts (exact reference semantics) ----
    {
        const int* __restrict__ ip = sq_idx + ((size_t)BATCH + b) * SEQLEN;
        const float4* __restrict__ tab1 = seq_tab + (size_t)VOCAB * 16;
        float4 acc = make_float4(0.f, 0.f, 0.f, 0.f);
        float4 cnt = make_float4(0.f, 0.f, 0.f, 0.f);
        #pragma unroll 10
        for (int s = 0; s < SEQLEN; s++) {
            int idx = __ldg(&ip[s]);
            float4 v = __ldg(&tab1[(size_t)idx * 16 + q]);
            acc.x += v.x; acc.y += v.y; acc.z += v.z; acc.w += v.w;
            cnt.x += (v.x != 0.f) ? 1.f : 0.f;
            cnt.y += (v.y != 0.f) ? 1.f : 0.f;
            cnt.z += (v.z != 0.f) ? 1.f : 0.f;
            cnt.w += (v.w != 0.f) ? 1.f : 0.f;
        }
        float* o = orow + (NSPARSE + 1) * EMBED + q * 4;
        o[0] = acc.x / (cnt.x + 1e-16f);
        o[1] = acc.y / (cnt.y + 1e-16f);
        o[2] = acc.z / (cnt.z + 1e-16f);
        o[3] = acc.w / (cnt.w + 1e-16f);
    }

    // ---- dense tail: 13 floats, lanes q=0..3 cover 4 each (last covers 1) ----
    {
        const float* __restrict__ drow = dense + (size_t)b * NDENSE;
        float* o = orow + (NSPARSE + 2) * EMBED;
        #pragma unroll
        for (int j4 = 0; j4 < 4; j4++) {
            int j = q * 4 + j4;
            if (j < NDENSE) o[j] = __ldg(&drow[j]);
        }
    }
}

extern "C" void kernel_launch(void* const* d_in, const int* in_sizes, int n_in,
                              void* d_out, int out_size) {
    const float* sp_tab  = (const float*)d_in[0];
    const float* seq_tab = (const float*)d_in[1];
    const float* dense   = (const float*)d_in[2];
    const int*   sp_idx  = (const int*)d_in[3];
    const int*   sq_idx  = (const int*)d_in[4];
    float*       out     = (float*)d_out;

    dim3 grid(BATCH / ROWS_PER_BLOCK);  // 256 blocks
    dim3 block(THREADS);                // 256 threads
    embedding_layer_kernel<<<grid, block>>>(
        (const float4*)sp_tab, (const float4*)seq_tab, dense, sp_idx, sq_idx, out);
}

// round 2
// speedup vs baseline: 1.2927x; 1.2927x over previous
#include <cuda_runtime.h>

// EmbeddingLayer: 16 sparse gathers + 2 sequence poolings (sum, nonzero-mean) + dense concat.
//
// Shapes:
//   sparse_tables [16, 100000, 64] f32
//   seq_tables    [ 2, 100000, 64] f32
//   dense_vals    [4096, 13]       f32
//   sparse_idx    [16, 4096]       i32
//   seq_idx       [ 2, 4096, 50]   i32
//   out           [4096, 1165]     f32
//
// R2: latency-bound fix. Two block families in one launch:
//   blocks [0, 4096): one block per batch row; thread (f,q) copies one float4
//                     of one sparse embedding row. Threads 0..12 copy dense.
//   blocks [4096, 5120): 8 warps/block; each warp owns one (row, feature) of
//                     sequence pooling. Lane = (q 0..15) x (half 0..1), each
//                     thread gathers 25 rows fully unrolled (MLP=25), halves
//                     merged with shfl_xor(16).

#define VOCAB   100000
#define BATCH   4096
#define EMBED   64
#define SEQLEN  50
#define NSPARSE 16
#define NDENSE  13
#define ROW_OUT (NSPARSE * EMBED + 2 * EMBED + NDENSE)  // 1165

#define SPARSE_BLOCKS  BATCH                 // 4096
#define SEQ_ROWS_PER_BLOCK 4                 // 4 rows x 2 features = 8 warps
#define SEQ_BLOCKS     (BATCH / SEQ_ROWS_PER_BLOCK)  // 1024
#define THREADS 256

__global__ __launch_bounds__(THREADS)
void embedding_layer_kernel(const float4* __restrict__ sp_tab,   // [16*VOCAB*16] float4
                            const float4* __restrict__ seq_tab,  // [ 2*VOCAB*16] float4
                            const float*  __restrict__ dense,    // [BATCH*13]
                            const int*    __restrict__ sp_idx,   // [16*BATCH]
                            const int*    __restrict__ sq_idx,   // [2*BATCH*50]
                            float*        __restrict__ out)      // [BATCH*1165]
{
    const int tid = threadIdx.x;

    if (blockIdx.x < SPARSE_BLOCKS) {
        // ---- sparse copy + dense tail: one block per batch row ----
        const int b = blockIdx.x;
        const int f = tid >> 4;      // feature 0..15
        const int q = tid & 15;      // float4 lane 0..15

        float* __restrict__ orow = out + (size_t)b * ROW_OUT;

        int idx = __ldg(&sp_idx[f * BATCH + b]);
        float4 v = __ldg(&sp_tab[((size_t)f * VOCAB + idx) * 16 + q]);
        float* o = orow + f * EMBED + q * 4;
        o[0] = v.x; o[1] = v.y; o[2] = v.z; o[3] = v.w;

        if (tid < NDENSE)
            orow[(NSPARSE + 2) * EMBED + tid] = __ldg(&dense[(size_t)b * NDENSE + tid]);
    } else {
        // ---- seq pooling: one warp per (batch row, feature) ----
        const int blk  = blockIdx.x - SPARSE_BLOCKS;     // 0..1023
        const int warp = tid >> 5;                       // 0..7
        const int lane = tid & 31;
        const int b    = blk * SEQ_ROWS_PER_BLOCK + (warp >> 1);
        const int feat = warp & 1;                       // 0: sum, 1: nonzero-mean
        const int q    = lane & 15;                      // float4 lane
        const int half = lane >> 4;                      // seq half: 0 -> [0,25), 1 -> [25,50)

        const int* __restrict__ ip =
            sq_idx + ((size_t)feat * BATCH + b) * SEQLEN + half * (SEQLEN / 2);
        const float4* __restrict__ tab = seq_tab + (size_t)feat * VOCAB * 16;

        float4 acc = make_float4(0.f, 0.f, 0.f, 0.f);
        float4 cnt = make_float4(0.f, 0.f, 0.f, 0.f);

        #pragma unroll
        for (int s = 0; s < SEQLEN / 2; s++) {
            int idx = __ldg(&ip[s]);
            float4 v = __ldg(&tab[(size_t)idx * 16 + q]);
            acc.x += v.x; acc.y += v.y; acc.z += v.z; acc.w += v.w;
            if (feat) {
                cnt.x += (v.x != 0.f) ? 1.f : 0.f;
                cnt.y += (v.y != 0.f) ? 1.f : 0.f;
                cnt.z += (v.z != 0.f) ? 1.f : 0.f;
                cnt.w += (v.w != 0.f) ? 1.f : 0.f;
            }
        }

        // merge the two seq-halves (lanes l and l^16 hold same q)
        acc.x += __shfl_xor_sync(0xFFFFFFFFu, acc.x, 16);
        acc.y += __shfl_xor_sync(0xFFFFFFFFu, acc.y, 16);
        acc.z += __shfl_xor_sync(0xFFFFFFFFu, acc.z, 16);
        acc.w += __shfl_xor_sync(0xFFFFFFFFu, acc.w, 16);
        if (feat) {
            cnt.x += __shfl_xor_sync(0xFFFFFFFFu, cnt.x, 16);
            cnt.y += __shfl_xor_sync(0xFFFFFFFFu, cnt.y, 16);
            cnt.z += __shfl_xor_sync(0xFFFFFFFFu, cnt.z, 16);
            cnt.w += __shfl_xor_sync(0xFFFFFFFFu, cnt.w, 16);
        }

        if (half == 0) {
            float* o = out + (size_t)b * ROW_OUT + (NSPARSE + feat) * EMBED + q * 4;
            if (feat == 0) {
                o[0] = acc.x; o[1] = acc.y; o[2] = acc.z; o[3] = acc.w;
            } else {
                o[0] = acc.x / (cnt.x + 1e-16f);
                o[1] = acc.y / (cnt.y + 1e-16f);
                o[2] = acc.z / (cnt.z + 1e-16f);
                o[3] = acc.w / (cnt.w + 1e-16f);
            }
        }
    }
}

extern "C" void kernel_launch(void* const* d_in, const int* in_sizes, int n_in,
                              void* d_out, int out_size) {
    const float* sp_tab  = (const float*)d_in[0];
    const float* seq_tab = (const float*)d_in[1];
    const float* dense   = (const float*)d_in[2];
    const int*   sp_idx  = (const int*)d_in[3];
    const int*   sq_idx  = (const int*)d_in[4];
    float*       out     = (float*)d_out;

    dim3 grid(SPARSE_BLOCKS + SEQ_BLOCKS);  // 5120 blocks
    dim3 block(THREADS);
    embedding_layer_kernel<<<grid, block>>>(
        (const float4*)sp_tab, (const float4*)seq_tab, dense, sp_idx, sq_idx, out);
}